// round 3
// baseline (speedup 1.0000x reference)
#include <cuda_runtime.h>
#include <math.h>

// Problem constants
constexpr int NN  = 50000;   // nodes
constexpr int DIN = 128;     // input feature dim
constexpr int HO  = 256;     // H*O
constexpr int NH  = 8;       // heads
constexpr int NE  = 400000;  // edges per path
constexpr int NP  = 3;       // metapaths
constexpr int HID = 128;     // semantic hidden

// ---------------- scratch (static device globals; no allocation) ----------------
__device__ float g_h  [(size_t)NP * NN * HO];   // per-path projected features
__device__ float g_out[(size_t)NP * NN * HO];   // per-path aggregated output (pre-activation)
__device__ float g_el [NP * NN * NH];
__device__ float g_er [NP * NN * NH];
__device__ float g_m  [NP * NN * NH];           // segment max
__device__ float g_s  [NP * NN * NH];           // segment sum -> reciprocal
__device__ float g_ew [(size_t)NP * NE * NH];   // exp(e - m[dst])
__device__ float g_wsum[NP];
__device__ float g_beta[NP];
__device__ int   g_is64;

// ---------------- helpers ----------------
__device__ __forceinline__ float elu_f(float x) { return x > 0.f ? x : expm1f(x); }

__device__ __forceinline__ float tanh_fast(float x) {
    float y;
    asm("tanh.approx.f32 %0, %1;" : "=f"(y) : "f"(x));
    return y;
}

// float atomic max via int/uint ordering trick (sign-bit branch handles +/-0)
__device__ __forceinline__ void atomicMaxF(float* addr, float v) {
    if ((__float_as_uint(v) >> 31) == 0)
        atomicMax((int*)addr, __float_as_int(v));
    else
        atomicMin((unsigned*)addr, __float_as_uint(v));
}

// edges may be int64 (jax x64) or int32 (x64 disabled) — uniform device branch
__device__ __forceinline__ int edge_val(const void* edges, size_t idx) {
    if (g_is64) return (int)(((const long long*)edges)[idx]);
    return ((const int*)edges)[idx];
}

// ---------------- kernels ----------------
__global__ void detect_kernel(const int* e32) {
    if (threadIdx.x == 0 && blockIdx.x == 0) {
        int is64 = 1;
        #pragma unroll
        for (int k = 0; k < 16; k++)
            if (e32[2 * k + 1] != 0) is64 = 0;
        g_is64 = is64;
    }
}

__global__ void init_kernel() {
    size_t i0 = (size_t)blockIdx.x * blockDim.x + threadIdx.x;
    size_t stride = (size_t)gridDim.x * blockDim.x;
    float4 z4 = make_float4(0.f, 0.f, 0.f, 0.f);
    float4* o4 = (float4*)g_out;
    size_t n4 = (size_t)NP * NN * HO / 4;
    for (size_t i = i0; i < n4; i += stride) o4[i] = z4;
    for (size_t i = i0; i < (size_t)NP * NN * NH; i += stride) {
        g_m[i] = -INFINITY;
        g_s[i] = 0.f;
    }
    if (i0 < NP) g_wsum[i0] = 0.f;
}

// h_p = feat @ W_p ; BM=64, BN=256(full), BK=16, thread tile 8x8, 256 thr
__global__ void __launch_bounds__(256) gemm_h(const float* __restrict__ feat,
                                              const float* __restrict__ Ws) {
    int p = blockIdx.y;
    int row0 = blockIdx.x * 64;
    const float* W = Ws + (size_t)p * DIN * HO;
    __shared__ float As[16][65];
    __shared__ float Bs[16][256];
    int tid = threadIdx.x;
    int tcol = tid & 31, trow = tid >> 5;

    float acc[8][8];
    #pragma unroll
    for (int i = 0; i < 8; i++)
        #pragma unroll
        for (int j = 0; j < 8; j++) acc[i][j] = 0.f;

    for (int k0 = 0; k0 < DIN; k0 += 16) {
        #pragma unroll
        for (int it = 0; it < 4; it++) {
            int l = tid + it * 256;
            int r = l >> 4, kk = l & 15;
            int gr = row0 + r;
            As[kk][r] = (gr < NN) ? feat[(size_t)gr * DIN + k0 + kk] : 0.f;
        }
        #pragma unroll
        for (int it = 0; it < 16; it++)
            Bs[it][tid] = W[(size_t)(k0 + it) * HO + tid];
        __syncthreads();
        #pragma unroll
        for (int kk = 0; kk < 16; kk++) {
            float a[8], b[8];
            #pragma unroll
            for (int i = 0; i < 8; i++) a[i] = As[kk][trow * 8 + i];
            #pragma unroll
            for (int j = 0; j < 8; j++) b[j] = Bs[kk][tcol + 32 * j];
            #pragma unroll
            for (int i = 0; i < 8; i++)
                #pragma unroll
                for (int j = 0; j < 8; j++) acc[i][j] += a[i] * b[j];
        }
        __syncthreads();
    }
    #pragma unroll
    for (int i = 0; i < 8; i++) {
        int gr = row0 + trow * 8 + i;
        if (gr >= NN) continue;
        float* hrow = g_h + ((size_t)p * NN + gr) * HO;
        #pragma unroll
        for (int j = 0; j < 8; j++) hrow[tcol + 32 * j] = acc[i][j];
    }
}

// el/er per (node, head): warp = head, lane = o
__global__ void elr_kernel(const float* __restrict__ al, const float* __restrict__ ar) {
    int p = blockIdx.y, n = blockIdx.x;
    int tid = threadIdx.x;
    int head = tid >> 5, lane = tid & 31;
    float v = g_h[((size_t)p * NN + n) * HO + tid];
    float xl = v * al[p * HO + tid];
    float xr = v * ar[p * HO + tid];
    #pragma unroll
    for (int off = 16; off; off >>= 1) {
        xl += __shfl_down_sync(0xffffffffu, xl, off);
        xr += __shfl_down_sync(0xffffffffu, xr, off);
    }
    if (lane == 0) {
        g_el[(p * NN + n) * NH + head] = xl;
        g_er[(p * NN + n) * NH + head] = xr;
    }
}

__global__ void edge_max(const void* __restrict__ edges) {
    int p = blockIdx.y;
    int idx = blockIdx.x * blockDim.x + threadIdx.x;
    if (idx >= NE * NH) return;
    int e = idx >> 3, hd = idx & 7;
    size_t base = (size_t)2 * p * NE;
    int src = edge_val(edges, base + e);
    int dst = edge_val(edges, base + NE + e);
    float x = g_el[(p * NN + src) * NH + hd] + g_er[(p * NN + dst) * NH + hd];
    x = x > 0.f ? x : 0.2f * x;
    atomicMaxF(&g_m[(p * NN + dst) * NH + hd], x);
}

__global__ void edge_exp(const void* __restrict__ edges) {
    int p = blockIdx.y;
    int idx = blockIdx.x * blockDim.x + threadIdx.x;
    if (idx >= NE * NH) return;
    int e = idx >> 3, hd = idx & 7;
    size_t base = (size_t)2 * p * NE;
    int src = edge_val(edges, base + e);
    int dst = edge_val(edges, base + NE + e);
    int di = (p * NN + dst) * NH + hd;
    float x = g_el[(p * NN + src) * NH + hd] + g_er[di];
    x = x > 0.f ? x : 0.2f * x;
    float w = __expf(x - g_m[di]);
    g_ew[((size_t)p * NE + e) * NH + hd] = w;
    atomicAdd(&g_s[di], w);
}

__global__ void rcp_kernel() {
    int i = blockIdx.x * blockDim.x + threadIdx.x;
    if (i < NP * NN * NH) {
        float s = g_s[i];
        g_s[i] = s > 0.f ? 1.0f / s : 0.f;
    }
}

// out[dst] += alpha * h[src] ; 4 edges/block, 64 threads/edge, red.v4
__global__ void agg_kernel(const void* __restrict__ edges) {
    int p = blockIdx.y;
    int g = threadIdx.x >> 6, t = threadIdx.x & 63;
    long long e = (long long)blockIdx.x * 4 + g;
    if (e >= NE) return;
    size_t base = (size_t)2 * p * NE;
    int src = edge_val(edges, base + e);
    int dst = edge_val(edges, base + NE + e);
    int head = t >> 3;
    float alpha = g_ew[((size_t)p * NE + e) * NH + head] *
                  g_s[(p * NN + dst) * NH + head];
    float4 hv = ((const float4*)(g_h + ((size_t)p * NN + src) * HO))[t];
    float* o = g_out + ((size_t)p * NN + dst) * HO + t * 4;
    asm volatile("red.global.add.v4.f32 [%0], {%1,%2,%3,%4};"
                 :: "l"(o), "f"(alpha * hv.x), "f"(alpha * hv.y),
                    "f"(alpha * hv.z), "f"(alpha * hv.w)
                 : "memory");
}

// semantic: wsum[p] += sum_n tanh(elu(out_p[n]+bias) @ W1 + b1) . w2
// BM=64, BN=128(full), BK=16, thread tile 8x4
__global__ void __launch_bounds__(256) sem_kernel(const float* __restrict__ bias,
                                                  const float* __restrict__ W1,
                                                  const float* __restrict__ b1,
                                                  const float* __restrict__ w2) {
    int p = blockIdx.y;
    int row0 = blockIdx.x * 64;
    __shared__ float As[16][65];
    __shared__ float Bs[16][128];
    __shared__ float red[8];
    int tid = threadIdx.x, tcol = tid & 31, trow = tid >> 5;
    const float* zb = g_out + (size_t)p * NN * HO;
    const float* bp = bias + p * HO;

    float acc[8][4];
    #pragma unroll
    for (int i = 0; i < 8; i++)
        #pragma unroll
        for (int j = 0; j < 4; j++) acc[i][j] = 0.f;

    for (int k0 = 0; k0 < HO; k0 += 16) {
        #pragma unroll
        for (int it = 0; it < 4; it++) {
            int l = tid + it * 256;
            int r = l >> 4, kk = l & 15;
            int gr = row0 + r;
            float v = 0.f;
            if (gr < NN) v = elu_f(zb[(size_t)gr * HO + k0 + kk] + bp[k0 + kk]);
            As[kk][r] = v;
        }
        #pragma unroll
        for (int it = 0; it < 8; it++) {
            int l = tid + it * 256;
            int kk = l >> 7, c = l & 127;
            Bs[kk][c] = W1[(size_t)(k0 + kk) * HID + c];
        }
        __syncthreads();
        #pragma unroll
        for (int kk = 0; kk < 16; kk++) {
            float a[8], b[4];
            #pragma unroll
            for (int i = 0; i < 8; i++) a[i] = As[kk][trow * 8 + i];
            #pragma unroll
            for (int j = 0; j < 4; j++) b[j] = Bs[kk][tcol + 32 * j];
            #pragma unroll
            for (int i = 0; i < 8; i++)
                #pragma unroll
                for (int j = 0; j < 4; j++) acc[i][j] += a[i] * b[j];
        }
        __syncthreads();
    }

    float part = 0.f;
    #pragma unroll
    for (int j = 0; j < 4; j++) {
        int c = tcol + 32 * j;
        float bb = b1[c], ww = w2[c];
        #pragma unroll
        for (int i = 0; i < 8; i++) {
            int gr = row0 + trow * 8 + i;
            if (gr < NN) part += tanh_fast(acc[i][j] + bb) * ww;
        }
    }
    #pragma unroll
    for (int off = 16; off; off >>= 1)
        part += __shfl_down_sync(0xffffffffu, part, off);
    if (tcol == 0) red[trow] = part;
    __syncthreads();
    if (tid == 0) {
        float s = 0.f;
        #pragma unroll
        for (int i = 0; i < 8; i++) s += red[i];
        atomicAdd(&g_wsum[p], s);
    }
}

__global__ void beta_kernel() {
    if (threadIdx.x == 0) {
        float w0 = g_wsum[0] / NN, w1 = g_wsum[1] / NN, w2v = g_wsum[2] / NN;
        float mx = fmaxf(w0, fmaxf(w1, w2v));
        float e0 = __expf(w0 - mx), e1 = __expf(w1 - mx), e2 = __expf(w2v - mx);
        float s = e0 + e1 + e2;
        g_beta[0] = e0 / s;
        g_beta[1] = e1 / s;
        g_beta[2] = e2 / s;
    }
}

__global__ void final_kernel(const float* __restrict__ bias, float* __restrict__ dout) {
    size_t i = (size_t)blockIdx.x * blockDim.x + threadIdx.x;  // float4 index
    size_t total = (size_t)NN * HO / 4;
    if (i >= total) return;
    int c4 = (int)(i & 63);
    float bw0 = g_beta[0], bw1 = g_beta[1], bw2 = g_beta[2];
    float bw[3] = {bw0, bw1, bw2};
    float4 r = make_float4(0.f, 0.f, 0.f, 0.f);
    #pragma unroll
    for (int p = 0; p < NP; p++) {
        float4 o = ((const float4*)g_out)[(size_t)p * NN * HO / 4 + i];
        const float* bp = bias + p * HO + c4 * 4;
        r.x += bw[p] * elu_f(o.x + bp[0]);
        r.y += bw[p] * elu_f(o.y + bp[1]);
        r.z += bw[p] * elu_f(o.z + bp[2]);
        r.w += bw[p] * elu_f(o.w + bp[3]);
    }
    ((float4*)dout)[i] = r;
}

// ---------------- launch ----------------
extern "C" void kernel_launch(void* const* d_in, const int* in_sizes, int n_in,
                              void* d_out, int out_size) {
    const float* feat  = (const float*)d_in[0];
    const void*  edges = d_in[1];
    const float* Ws    = (const float*)d_in[2];
    const float* al    = (const float*)d_in[3];
    const float* ar    = (const float*)d_in[4];
    const float* bias  = (const float*)d_in[5];
    const float* W1    = (const float*)d_in[6];
    const float* b1    = (const float*)d_in[7];
    const float* w2    = (const float*)d_in[8];
    float* outp = (float*)d_out;

    detect_kernel<<<1, 32>>>((const int*)edges);
    init_kernel<<<2048, 256>>>();

    dim3 gh((NN + 63) / 64, NP);
    gemm_h<<<gh, 256>>>(feat, Ws);

    elr_kernel<<<dim3(NN, NP), 256>>>(al, ar);

    dim3 ge((NE * NH + 255) / 256, NP);
    edge_max<<<ge, 256>>>(edges);
    edge_exp<<<ge, 256>>>(edges);

    rcp_kernel<<<(NP * NN * NH + 255) / 256, 256>>>();

    agg_kernel<<<dim3((NE + 3) / 4, NP), 256>>>(edges);

    sem_kernel<<<dim3((NN + 63) / 64, NP), 256>>>(bias, W1, b1, w2);
    beta_kernel<<<1, 32>>>();

    final_kernel<<<(int)(((size_t)NN * HO / 4 + 255) / 256), 256>>>(bias, outp);
}